// round 8
// baseline (speedup 1.0000x reference)
#include <cuda_runtime.h>
#include <cuda_bf16.h>
#include <cstdint>

// Problem constants
#define PN 8192      // batch rows
#define PC 1024      // feature dim
#define PS 8192      // negatives (sampled)
#define PUNITS 128000

#define WSCALE 64.0f          // W pre-scale into e4m3 normal range
#define INV_WSCALE 0.015625f  // 1/64 applied to accumulators

// ---------------- device scratch (static, allocation-free) ----------------
__device__ uint8_t g_X8[PN * PC];   // inputs in e4m3                (8 MB)
__device__ uint8_t g_W8[PS * PC];   // gathered sampled rows * 64     (8 MB)
__device__ float g_bcorr[PS];       // bias[sampled] - log(E(sampled))
__device__ float g_true[PN];        // corrected true logits (fp32 exact)
__device__ float g_rowsum[PN];      // sum_s exp(corrected samp logit)

// ---------------- helpers ----------------
__device__ __forceinline__ float neg_log_expected(int id) {
    float idf = (float)id;
    float p = (logf(idf + 2.0f) - logf(idf + 1.0f)) / logf((float)(PUNITS + 1));
    float e = -expm1f((float)PS * log1pf(-p));
    return -logf(e);
}

// pack 4 floats -> 4 e4m3 bytes (byte0=a .. byte3=d)
__device__ __forceinline__ uint32_t f4_to_e4m3(float a, float b, float c, float d) {
    uint16_t lo, hi;
    asm("cvt.rn.satfinite.e4m3x2.f32 %0, %1, %2;" : "=h"(lo) : "f"(b), "f"(a));
    asm("cvt.rn.satfinite.e4m3x2.f32 %0, %1, %2;" : "=h"(hi) : "f"(d), "f"(c));
    return (uint32_t)lo | ((uint32_t)hi << 16);
}

__device__ __forceinline__ void ldm_x4(uint32_t (&r)[4], uint32_t saddr) {
    asm volatile("ldmatrix.sync.aligned.m8n8.x4.shared.b16 {%0,%1,%2,%3}, [%4];"
                 : "=r"(r[0]), "=r"(r[1]), "=r"(r[2]), "=r"(r[3])
                 : "r"(saddr));
}

__device__ __forceinline__ void mma_fp8(float (&c)[4], const uint32_t (&a)[4],
                                        const uint32_t b0, const uint32_t b1) {
    asm volatile(
        "mma.sync.aligned.m16n8k32.row.col.f32.e4m3.e4m3.f32 "
        "{%0,%1,%2,%3}, {%4,%5,%6,%7}, {%8,%9}, {%0,%1,%2,%3};"
        : "+f"(c[0]), "+f"(c[1]), "+f"(c[2]), "+f"(c[3])
        : "r"(a[0]), "r"(a[1]), "r"(a[2]), "r"(a[3]), "r"(b0), "r"(b1));
}

#define CP_ASYNC16(dst, src) \
    asm volatile("cp.async.cg.shared.global [%0], [%1], 16;" :: "r"(dst), "l"(src))

// ---------------- prep: e4m3 convert inputs + gather sampled W rows ----------------
__global__ void prep_gather_kernel(const float* __restrict__ inputs,
                                   const int* __restrict__ sampled,
                                   const float* __restrict__ kern) {
    const int total4 = (PN * PC) / 4;
    for (int i = blockIdx.x * blockDim.x + threadIdx.x; i < total4;
         i += gridDim.x * blockDim.x) {
        float4 x = ((const float4*)inputs)[i];
        ((uint32_t*)g_X8)[i] = f4_to_e4m3(x.x, x.y, x.z, x.w);

        int s  = i >> 8;      // (i*4)/1024
        int c4 = i & 255;
        float4 w = ((const float4*)(kern + ((size_t)sampled[s] << 10)))[c4];
        ((uint32_t*)g_W8)[i] = f4_to_e4m3(w.x * WSCALE, w.y * WSCALE,
                                          w.z * WSCALE, w.w * WSCALE);
    }
}

// ---------------- prep: sampled bias + correction ----------------
__global__ void prep_bcorr_kernel(const int* __restrict__ sampled,
                                  const float* __restrict__ bias) {
    int s = blockIdx.x * blockDim.x + threadIdx.x;
    if (s < PS) {
        int sid = sampled[s];
        g_bcorr[s] = bias[sid] + neg_log_expected(sid);
    }
}

// ---------------- prep: true logits (fp32 exact) + zero rowsums ----------------
__global__ void prep_true_kernel(const float* __restrict__ inputs,
                                 const int* __restrict__ targets,
                                 const float* __restrict__ kern,
                                 const float* __restrict__ bias) {
    int warp = threadIdx.x >> 5, lane = threadIdx.x & 31;
    int n = blockIdx.x * 8 + warp;
    if (n >= PN) return;
    int tgt = targets[n];
    const float4* xr = (const float4*)(inputs + ((size_t)n << 10));
    const float4* wr = (const float4*)(kern + ((size_t)tgt << 10));
    float d = 0.f;
#pragma unroll
    for (int it = 0; it < 8; ++it) {
        float4 a = xr[lane + it * 32];
        float4 b = wr[lane + it * 32];
        d += a.x * b.x + a.y * b.y + a.z * b.z + a.w * b.w;
    }
#pragma unroll
    for (int o = 16; o; o >>= 1) d += __shfl_down_sync(0xffffffffu, d, o);
    if (lane == 0) {
        g_true[n] = d + bias[tgt] + neg_log_expected(tgt);
        g_rowsum[n] = 0.f;
    }
}

// ---------------- fused FP8 GEMM + exp epilogue ----------------
// CTA tile 128(M) x 256(N), K-chunk 64 bytes. 8 warps in 2(M) x 4(N),
// warp tile 64x64 via mma.m16n8k32.e4m3. 4-stage cp.async pipeline.
#define SLDB 80                         // smem row stride bytes (64 + 16 pad)
#define A_STG (128 * SLDB)              // 10240
#define B_STG (256 * SLDB)              // 20480
#define NSTG 4
#define OFF_B    (NSTG * A_STG)         // 40960
#define OFF_SROW (OFF_B + NSTG * B_STG) // 122880
#define SMEM_BYTES (OFF_SROW + 512)
#define NK (PC / 64)                    // 16 K-chunks

__global__ __launch_bounds__(256, 1) void gemm_exp_kernel(
    const int* __restrict__ targets, const int* __restrict__ sampled) {
    extern __shared__ char smem[];
    float* srow = (float*)(smem + OFF_SROW);

    const int tid = threadIdx.x;
    const int lane = tid & 31, warp = tid >> 5;
    const int wm = warp >> 2, wn = warp & 3;     // 2 x 4 warp grid
    const int bm = blockIdx.y * 128, bn = blockIdx.x * 256;

    float acc[4][8][4];
#pragma unroll
    for (int mi = 0; mi < 4; mi++)
#pragma unroll
        for (int ni = 0; ni < 8; ni++)
#pragma unroll
            for (int e = 0; e < 4; e++) acc[mi][ni][e] = 0.f;

    if (tid < 128) srow[tid] = 0.f;

    uint32_t sbase;
    asm("{ .reg .u64 t; cvta.to.shared.u64 t, %1; cvt.u32.u64 %0, t; }"
        : "=r"(sbase) : "l"(smem));
    const uint32_t sA = sbase;
    const uint32_t sB = sbase + OFF_B;

    // ldmatrix per-lane addressing (fp8: 16-byte columns)
    // A: reg order {m0k0, m1k0, m0k1, m1k1}
    const int arow  = wm * 64 + (lane & 7) + 8 * ((lane >> 3) & 1);
    const int acoff = (lane >> 4) * 16;
    // B: reg order {n0k0, n0k1, n1k0, n1k1}
    const int brow  = wn * 64 + (lane & 7) + 8 * (lane >> 4);
    const int bcoff = ((lane >> 3) & 1) * 16;

    // global->shared: A 512 chunks (2/thread), B 1024 chunks (4/thread)
    const int ar = tid >> 2, ac = tid & 3;                    // A chunk tid
    const uint8_t* AgBase = g_X8 + (size_t)(bm + ar) * PC + ac * 16;
    const uint32_t dA0 = sA + (uint32_t)(ar * SLDB + ac * 16);
    // B rows for chunks tid, tid+256, tid+512, tid+768 -> rows ar, ar+64, ...
    const uint8_t* BgBase = g_W8 + (size_t)(bn + ar) * PC + ac * 16;
    const uint32_t dB0 = sB + (uint32_t)(ar * SLDB + ac * 16);

#define LOAD_STAGE(kt_)                                                        \
    do {                                                                       \
        if ((kt_) < NK) {                                                      \
            uint32_t so_a = (uint32_t)((kt_) & 3) * A_STG;                     \
            uint32_t so_b = (uint32_t)((kt_) & 3) * B_STG;                     \
            int ko = (kt_) * 64;                                               \
            CP_ASYNC16(dA0 + so_a, AgBase + ko);                               \
            CP_ASYNC16(dA0 + so_a + 64 * SLDB, AgBase + ko + (size_t)64 * PC); \
            CP_ASYNC16(dB0 + so_b, BgBase + ko);                               \
            CP_ASYNC16(dB0 + so_b + 64 * SLDB, BgBase + ko + (size_t)64 * PC); \
            CP_ASYNC16(dB0 + so_b + 128 * SLDB, BgBase + ko + (size_t)128 * PC); \
            CP_ASYNC16(dB0 + so_b + 192 * SLDB, BgBase + ko + (size_t)192 * PC); \
        }                                                                      \
        asm volatile("cp.async.commit_group;" ::: "memory");                   \
    } while (0)

    LOAD_STAGE(0);
    LOAD_STAGE(1);
    LOAD_STAGE(2);

#pragma unroll 1
    for (int kt = 0; kt < NK; ++kt) {
        asm volatile("cp.async.wait_group 2;" ::: "memory");
        __syncthreads();

        LOAD_STAGE(kt + 3);

        const uint32_t aoff = sA + (uint32_t)(kt & 3) * A_STG;
        const uint32_t boff = sB + (uint32_t)(kt & 3) * B_STG;

#pragma unroll
        for (int ks = 0; ks < 2; ++ks) {
            uint32_t a[4][4];
            uint32_t b[8][2];
#pragma unroll
            for (int mi = 0; mi < 4; mi++) {
                uint32_t addr = aoff +
                    (uint32_t)((arow + mi * 16) * SLDB + ks * 32 + acoff);
                ldm_x4(a[mi], addr);
            }
#pragma unroll
            for (int nb = 0; nb < 4; nb++) {
                uint32_t r[4];
                uint32_t addr = boff +
                    (uint32_t)((brow + nb * 16) * SLDB + ks * 32 + bcoff);
                ldm_x4(r, addr);
                b[2 * nb][0] = r[0];
                b[2 * nb][1] = r[1];
                b[2 * nb + 1][0] = r[2];
                b[2 * nb + 1][1] = r[3];
            }
#pragma unroll
            for (int mi = 0; mi < 4; mi++)
#pragma unroll
                for (int ni = 0; ni < 8; ni++)
                    mma_fp8(acc[mi][ni], a[mi], b[ni][0], b[ni][1]);
        }
    }

    // ---- epilogue: scale, correct, mask, exp, per-row partial sums ----
    int tg[4][2];
#pragma unroll
    for (int mi = 0; mi < 4; mi++)
#pragma unroll
        for (int h = 0; h < 2; h++)
            tg[mi][h] = targets[bm + wm * 64 + mi * 16 + (lane >> 2) + h * 8];

    float rs[4][2];
#pragma unroll
    for (int mi = 0; mi < 4; mi++) { rs[mi][0] = 0.f; rs[mi][1] = 0.f; }

#pragma unroll
    for (int ni = 0; ni < 8; ni++) {
#pragma unroll
        for (int j = 0; j < 2; j++) {
            int col = bn + wn * 64 + ni * 8 + ((lane & 3) << 1) + j;
            int sid = sampled[col];
            float bc = g_bcorr[col];
#pragma unroll
            for (int mi = 0; mi < 4; mi++) {
#pragma unroll
                for (int h = 0; h < 2; h++) {
                    if (sid != tg[mi][h])
                        rs[mi][h] += __expf(acc[mi][ni][h * 2 + j] * INV_WSCALE + bc);
                }
            }
        }
    }

#pragma unroll
    for (int mi = 0; mi < 4; mi++) {
#pragma unroll
        for (int h = 0; h < 2; h++) {
            float v = rs[mi][h];
            v += __shfl_xor_sync(0xffffffffu, v, 1);
            v += __shfl_xor_sync(0xffffffffu, v, 2);
            if ((lane & 3) == 0)
                atomicAdd(&srow[wm * 64 + mi * 16 + (lane >> 2) + h * 8], v);
        }
    }
    __syncthreads();
    if (tid < 128) atomicAdd(&g_rowsum[bm + tid], srow[tid]);
}

// ---------------- finalize: per-example loss + mean ----------------
__global__ void finalize_kernel(float* __restrict__ out) {
    __shared__ double sh[32];
    double local = 0.0;
    for (int n = threadIdx.x; n < PN; n += 1024) {
        float t = g_true[n];
        float v = logf(g_rowsum[n] + expf(t)) - t;
        local += (double)v;
    }
#pragma unroll
    for (int o = 16; o; o >>= 1) local += __shfl_down_sync(0xffffffffu, local, o);
    if ((threadIdx.x & 31) == 0) sh[threadIdx.x >> 5] = local;
    __syncthreads();
    if (threadIdx.x < 32) {
        double v = sh[threadIdx.x];
#pragma unroll
        for (int o = 16; o; o >>= 1) v += __shfl_down_sync(0xffffffffu, v, o);
        if (threadIdx.x == 0) out[0] = (float)(v / (double)PN);
    }
}

// ---------------- entry ----------------
extern "C" void kernel_launch(void* const* d_in, const int* in_sizes, int n_in,
                              void* d_out, int out_size) {
    const float* inputs  = (const float*)d_in[0];
    const int*   targets = (const int*)d_in[1];
    const int*   sampled = (const int*)d_in[2];
    const float* kern    = (const float*)d_in[3];
    const float* bias    = (const float*)d_in[4];
    float* out = (float*)d_out;

    static int smem_set = 0;
    if (!smem_set) {
        cudaFuncSetAttribute(gemm_exp_kernel,
                             cudaFuncAttributeMaxDynamicSharedMemorySize, SMEM_BYTES);
        smem_set = 1;
    }

    prep_gather_kernel<<<4096, 256>>>(inputs, sampled, kern);
    prep_bcorr_kernel<<<PS / 256, 256>>>(sampled, bias);
    prep_true_kernel<<<PN / 8, 256>>>(inputs, targets, kern, bias);

    dim3 grid(PS / 256, PN / 128);
    gemm_exp_kernel<<<grid, 256, SMEM_BYTES>>>(targets, sampled);

    finalize_kernel<<<1, 1024>>>(out);
}

// round 9
// speedup vs baseline: 1.1552x; 1.1552x over previous
#include <cuda_runtime.h>
#include <cuda_bf16.h>
#include <cstdint>

// Problem constants
#define PN 8192      // batch rows
#define PC 1024      // feature dim
#define PS 8192      // negatives (sampled)
#define PUNITS 128000

// ---------------- device scratch (static, allocation-free) ----------------
__device__ __nv_bfloat16 g_X[PN * PC];   // inputs in bf16           (16 MB)
__device__ __nv_bfloat16 g_W[PS * PC];   // gathered sampled rows    (16 MB)
__device__ float g_bcorr[PS];            // bias[sampled] - log(E(sampled))
__device__ float g_true[PN];             // corrected true logits
__device__ float g_rowsum[PN];           // sum_s exp(corrected samp logit)

// ---------------- helpers ----------------
__device__ __forceinline__ float neg_log_expected(int id) {
    float idf = (float)id;
    float p = (logf(idf + 2.0f) - logf(idf + 1.0f)) / logf((float)(PUNITS + 1));
    float e = -expm1f((float)PS * log1pf(-p));
    return -logf(e);
}

__device__ __forceinline__ void ldm_x4(uint32_t (&r)[4], uint32_t saddr) {
    asm volatile("ldmatrix.sync.aligned.m8n8.x4.shared.b16 {%0,%1,%2,%3}, [%4];"
                 : "=r"(r[0]), "=r"(r[1]), "=r"(r[2]), "=r"(r[3])
                 : "r"(saddr));
}

__device__ __forceinline__ void mma_bf16(float (&c)[4], const uint32_t (&a)[4],
                                         const uint32_t b0, const uint32_t b1) {
    asm volatile(
        "mma.sync.aligned.m16n8k16.row.col.f32.bf16.bf16.f32 "
        "{%0,%1,%2,%3}, {%4,%5,%6,%7}, {%8,%9}, {%0,%1,%2,%3};"
        : "+f"(c[0]), "+f"(c[1]), "+f"(c[2]), "+f"(c[3])
        : "r"(a[0]), "r"(a[1]), "r"(a[2]), "r"(a[3]), "r"(b0), "r"(b1));
}

#define CP_ASYNC16(dst, src) \
    asm volatile("cp.async.cg.shared.global [%0], [%1], 16;" :: "r"(dst), "l"(src))

// ---------------- prep: bf16 convert inputs + gather sampled W rows ----------------
__global__ void prep_gather_kernel(const float* __restrict__ inputs,
                                   const int* __restrict__ sampled,
                                   const float* __restrict__ kern) {
    const int total4 = (PN * PC) / 4;
    for (int i = blockIdx.x * blockDim.x + threadIdx.x; i < total4;
         i += gridDim.x * blockDim.x) {
        float4 x = ((const float4*)inputs)[i];
        __nv_bfloat162* dx = (__nv_bfloat162*)g_X + (size_t)i * 2;
        dx[0] = __floats2bfloat162_rn(x.x, x.y);
        dx[1] = __floats2bfloat162_rn(x.z, x.w);

        int s  = i >> 8;
        int c4 = i & 255;
        float4 w = ((const float4*)(kern + ((size_t)sampled[s] << 10)))[c4];
        __nv_bfloat162* dw = (__nv_bfloat162*)g_W + (size_t)i * 2;
        dw[0] = __floats2bfloat162_rn(w.x, w.y);
        dw[1] = __floats2bfloat162_rn(w.z, w.w);
    }
}

// ---------------- prep: sampled bias + correction ----------------
__global__ void prep_bcorr_kernel(const int* __restrict__ sampled,
                                  const float* __restrict__ bias) {
    int s = blockIdx.x * blockDim.x + threadIdx.x;
    if (s < PS) {
        int sid = sampled[s];
        g_bcorr[s] = bias[sid] + neg_log_expected(sid);
    }
}

// ---------------- prep: true logits (fp32) + zero rowsums ----------------
__global__ void prep_true_kernel(const float* __restrict__ inputs,
                                 const int* __restrict__ targets,
                                 const float* __restrict__ kern,
                                 const float* __restrict__ bias) {
    int warp = threadIdx.x >> 5, lane = threadIdx.x & 31;
    int n = blockIdx.x * 8 + warp;
    if (n >= PN) return;
    int tgt = targets[n];
    const float4* xr = (const float4*)(inputs + ((size_t)n << 10));
    const float4* wr = (const float4*)(kern + ((size_t)tgt << 10));
    float d = 0.f;
#pragma unroll
    for (int it = 0; it < 8; ++it) {
        float4 a = xr[lane + it * 32];
        float4 b = wr[lane + it * 32];
        d += a.x * b.x + a.y * b.y + a.z * b.z + a.w * b.w;
    }
#pragma unroll
    for (int o = 16; o; o >>= 1) d += __shfl_down_sync(0xffffffffu, d, o);
    if (lane == 0) {
        g_true[n] = d + bias[tgt] + neg_log_expected(tgt);
        g_rowsum[n] = 0.f;
    }
}

// ---------------- fused GEMM (bf16 mma.sync) + exp epilogue ----------------
// CTA tile 128x128, 4 warps in 2(M) x 2(N), warp tile 64x64.
// K-chunk 32, 4-stage cp.async pipeline, 2 CTAs/SM.
#define SLD 40                         // smem K stride (32 + 8 pad) in bf16
#define STG_BYTES (128 * SLD * 2)      // 10240 B per operand stage
#define NSTG 4
#define OFF_B    (NSTG * STG_BYTES)    // 40960
#define OFF_SROW (2 * NSTG * STG_BYTES)// 81920
#define SMEM_BYTES (OFF_SROW + 512)
#define NK (PC / 32)                   // 32 K-chunks

__global__ __launch_bounds__(128, 2) void gemm_exp_kernel(
    const int* __restrict__ targets, const int* __restrict__ sampled) {
    extern __shared__ char smem[];
    float* srow = (float*)(smem + OFF_SROW);

    const int tid = threadIdx.x;
    const int lane = tid & 31, warp = tid >> 5;
    const int wm = warp >> 1, wn = warp & 1;       // 2 x 2 warp grid
    const int bm = blockIdx.y * 128, bn = blockIdx.x * 128;

    float acc[4][8][4];
#pragma unroll
    for (int mi = 0; mi < 4; mi++)
#pragma unroll
        for (int ni = 0; ni < 8; ni++)
#pragma unroll
            for (int e = 0; e < 4; e++) acc[mi][ni][e] = 0.f;

    srow[tid] = 0.f;

    uint32_t sbase;
    asm("{ .reg .u64 t; cvta.to.shared.u64 t, %1; cvt.u32.u64 %0, t; }"
        : "=r"(sbase) : "l"(smem));
    const uint32_t sA = sbase;
    const uint32_t sB = sbase + OFF_B;

    // ldmatrix per-lane address components (within tile)
    const int arow  = wm * 64 + (lane & 7) + 8 * ((lane >> 3) & 1);
    const int acoff = (lane >> 4) * 8;
    const int brow  = wn * 64 + (lane & 7) + 8 * (lane >> 4);
    const int bcoff = ((lane >> 3) & 1) * 8;

    // global->shared: 512 16B chunks per operand per stage, 4 per thread
    const int r0 = tid >> 2, c0 = tid & 3;   // rows r0, r0+32, r0+64, r0+96
    const __nv_bfloat16* Ag = g_X + (size_t)(bm + r0) * PC + c0 * 8;
    const __nv_bfloat16* Bg = g_W + (size_t)(bn + r0) * PC + c0 * 8;
    const uint32_t dA = sA + (uint32_t)(r0 * SLD + c0 * 8) * 2;
    const uint32_t dB = sB + (uint32_t)(r0 * SLD + c0 * 8) * 2;

#define LOAD_STAGE(kt_)                                                        \
    do {                                                                       \
        if ((kt_) < NK) {                                                      \
            uint32_t so = (uint32_t)((kt_) & 3) * STG_BYTES;                   \
            int ko = (kt_) * 32;                                               \
            _Pragma("unroll")                                                  \
            for (int it = 0; it < 4; ++it) {                                   \
                CP_ASYNC16(dA + so + (uint32_t)(it * 32 * SLD * 2),            \
                           Ag + ko + (size_t)it * 32 * PC);                    \
                CP_ASYNC16(dB + so + (uint32_t)(it * 32 * SLD * 2),            \
                           Bg + ko + (size_t)it * 32 * PC);                    \
            }                                                                  \
        }                                                                      \
        asm volatile("cp.async.commit_group;" ::: "memory");                   \
    } while (0)

    LOAD_STAGE(0);
    LOAD_STAGE(1);
    LOAD_STAGE(2);

#pragma unroll 1
    for (int kt = 0; kt < NK; ++kt) {
        asm volatile("cp.async.wait_group 2;" ::: "memory");
        __syncthreads();

        LOAD_STAGE(kt + 3);

        const uint32_t aoff = sA + (uint32_t)(kt & 3) * STG_BYTES;
        const uint32_t boff = sB + (uint32_t)(kt & 3) * STG_BYTES;

#pragma unroll
        for (int ks = 0; ks < 2; ++ks) {
            uint32_t a[4][4];
            uint32_t b[8][2];
#pragma unroll
            for (int mi = 0; mi < 4; mi++) {
                uint32_t addr = aoff +
                    (uint32_t)(((arow + mi * 16) * SLD + ks * 16 + acoff) * 2);
                ldm_x4(a[mi], addr);
            }
#pragma unroll
            for (int nb = 0; nb < 4; nb++) {
                uint32_t r[4];
                uint32_t addr = boff +
                    (uint32_t)(((brow + nb * 16) * SLD + ks * 16 + bcoff) * 2);
                ldm_x4(r, addr);
                b[2 * nb][0] = r[0];
                b[2 * nb][1] = r[1];
                b[2 * nb + 1][0] = r[2];
                b[2 * nb + 1][1] = r[3];
            }
#pragma unroll
            for (int mi = 0; mi < 4; mi++)
#pragma unroll
                for (int ni = 0; ni < 8; ni++)
                    mma_bf16(acc[mi][ni], a[mi], b[ni][0], b[ni][1]);
        }
    }

    // ---- epilogue: corrected logits -> exp -> per-row partial sums ----
    int tg[4][2];
#pragma unroll
    for (int mi = 0; mi < 4; mi++)
#pragma unroll
        for (int h = 0; h < 2; h++)
            tg[mi][h] = targets[bm + wm * 64 + mi * 16 + (lane >> 2) + h * 8];

    float rs[4][2];
#pragma unroll
    for (int mi = 0; mi < 4; mi++) { rs[mi][0] = 0.f; rs[mi][1] = 0.f; }

#pragma unroll
    for (int ni = 0; ni < 8; ni++) {
#pragma unroll
        for (int j = 0; j < 2; j++) {
            int col = bn + wn * 64 + ni * 8 + ((lane & 3) << 1) + j;
            int sid = sampled[col];
            float bc = g_bcorr[col];
#pragma unroll
            for (int mi = 0; mi < 4; mi++) {
#pragma unroll
                for (int h = 0; h < 2; h++) {
                    if (sid != tg[mi][h])
                        rs[mi][h] += __expf(acc[mi][ni][h * 2 + j] + bc);
                }
            }
        }
    }

#pragma unroll
    for (int mi = 0; mi < 4; mi++) {
#pragma unroll
        for (int h = 0; h < 2; h++) {
            float v = rs[mi][h];
            v += __shfl_xor_sync(0xffffffffu, v, 1);
            v += __shfl_xor_sync(0xffffffffu, v, 2);
            if ((lane & 3) == 0)
                atomicAdd(&srow[wm * 64 + mi * 16 + (lane >> 2) + h * 8], v);
        }
    }
    __syncthreads();
    atomicAdd(&g_rowsum[bm + tid], srow[tid]);
}

// ---------------- finalize: per-example loss + mean ----------------
__global__ void finalize_kernel(float* __restrict__ out) {
    __shared__ double sh[32];
    double local = 0.0;
    for (int n = threadIdx.x; n < PN; n += 1024) {
        float t = g_true[n];
        float v = logf(g_rowsum[n] + expf(t)) - t;
        local += (double)v;
    }
#pragma unroll
    for (int o = 16; o; o >>= 1) local += __shfl_down_sync(0xffffffffu, local, o);
    if ((threadIdx.x & 31) == 0) sh[threadIdx.x >> 5] = local;
    __syncthreads();
    if (threadIdx.x < 32) {
        double v = sh[threadIdx.x];
#pragma unroll
        for (int o = 16; o; o >>= 1) v += __shfl_down_sync(0xffffffffu, v, o);
        if (threadIdx.x == 0) out[0] = (float)(v / (double)PN);
    }
}

// ---------------- entry ----------------
extern "C" void kernel_launch(void* const* d_in, const int* in_sizes, int n_in,
                              void* d_out, int out_size) {
    const float* inputs  = (const float*)d_in[0];
    const int*   targets = (const int*)d_in[1];
    const int*   sampled = (const int*)d_in[2];
    const float* kern    = (const float*)d_in[3];
    const float* bias    = (const float*)d_in[4];
    float* out = (float*)d_out;

    static int smem_set = 0;
    if (!smem_set) {
        cudaFuncSetAttribute(gemm_exp_kernel,
                             cudaFuncAttributeMaxDynamicSharedMemorySize, SMEM_BYTES);
        smem_set = 1;
    }

    prep_gather_kernel<<<4096, 256>>>(inputs, sampled, kern);
    prep_bcorr_kernel<<<PS / 256, 256>>>(sampled, bias);
    prep_true_kernel<<<PN / 8, 256>>>(inputs, targets, kern, bias);

    dim3 grid(PS / 128, PN / 128);
    gemm_exp_kernel<<<grid, 128, SMEM_BYTES>>>(targets, sampled);

    finalize_kernel<<<1, 1024>>>(out);
}

// round 10
// speedup vs baseline: 1.3103x; 1.1343x over previous
#include <cuda_runtime.h>
#include <cuda_bf16.h>
#include <cstdint>

// Problem constants
#define PN 8192      // batch rows
#define PC 1024      // feature dim
#define PS 8192      // negatives (sampled)
#define PUNITS 128000

// ---------------- device scratch (static, allocation-free) ----------------
__device__ __nv_bfloat16 g_X[PN * PC];   // inputs in bf16           (16 MB)
__device__ __nv_bfloat16 g_W[PS * PC];   // gathered sampled rows    (16 MB)
__device__ float g_bcorr[PS];            // bias[sampled] - log(E(sampled))
__device__ float g_true[PN];             // corrected true logits
__device__ float g_rowsum[PN];           // sum_s exp(corrected samp logit)

// ---------------- helpers ----------------
__device__ __forceinline__ float neg_log_expected(int id) {
    float idf = (float)id;
    float p = (logf(idf + 2.0f) - logf(idf + 1.0f)) / logf((float)(PUNITS + 1));
    float e = -expm1f((float)PS * log1pf(-p));
    return -logf(e);
}

__device__ __forceinline__ void ldm_x4(uint32_t (&r)[4], uint32_t saddr) {
    asm volatile("ldmatrix.sync.aligned.m8n8.x4.shared.b16 {%0,%1,%2,%3}, [%4];"
                 : "=r"(r[0]), "=r"(r[1]), "=r"(r[2]), "=r"(r[3])
                 : "r"(saddr));
}

__device__ __forceinline__ void mma_bf16(float (&c)[4], const uint32_t (&a)[4],
                                         const uint32_t b0, const uint32_t b1) {
    asm volatile(
        "mma.sync.aligned.m16n8k16.row.col.f32.bf16.bf16.f32 "
        "{%0,%1,%2,%3}, {%4,%5,%6,%7}, {%8,%9}, {%0,%1,%2,%3};"
        : "+f"(c[0]), "+f"(c[1]), "+f"(c[2]), "+f"(c[3])
        : "r"(a[0]), "r"(a[1]), "r"(a[2]), "r"(a[3]), "r"(b0), "r"(b1));
}

#define CP_ASYNC16(dst, src) \
    asm volatile("cp.async.cg.shared.global [%0], [%1], 16;" :: "r"(dst), "l"(src))

// ---------------- prep: bf16 convert inputs + gather sampled W rows ----------------
__global__ void prep_gather_kernel(const float* __restrict__ inputs,
                                   const int* __restrict__ sampled,
                                   const float* __restrict__ kern) {
    const int total4 = (PN * PC) / 4;
    for (int i = blockIdx.x * blockDim.x + threadIdx.x; i < total4;
         i += gridDim.x * blockDim.x) {
        float4 x = ((const float4*)inputs)[i];
        __nv_bfloat162* dx = (__nv_bfloat162*)g_X + (size_t)i * 2;
        dx[0] = __floats2bfloat162_rn(x.x, x.y);
        dx[1] = __floats2bfloat162_rn(x.z, x.w);

        int s  = i >> 8;
        int c4 = i & 255;
        float4 w = ((const float4*)(kern + ((size_t)sampled[s] << 10)))[c4];
        __nv_bfloat162* dw = (__nv_bfloat162*)g_W + (size_t)i * 2;
        dw[0] = __floats2bfloat162_rn(w.x, w.y);
        dw[1] = __floats2bfloat162_rn(w.z, w.w);
    }
}

// ---------------- prep: sampled bias + correction ----------------
__global__ void prep_bcorr_kernel(const int* __restrict__ sampled,
                                  const float* __restrict__ bias) {
    int s = blockIdx.x * blockDim.x + threadIdx.x;
    if (s < PS) {
        int sid = sampled[s];
        g_bcorr[s] = bias[sid] + neg_log_expected(sid);
    }
}

// ---------------- prep: true logits (fp32) + zero rowsums ----------------
__global__ void prep_true_kernel(const float* __restrict__ inputs,
                                 const int* __restrict__ targets,
                                 const float* __restrict__ kern,
                                 const float* __restrict__ bias) {
    int warp = threadIdx.x >> 5, lane = threadIdx.x & 31;
    int n = blockIdx.x * 8 + warp;
    if (n >= PN) return;
    int tgt = targets[n];
    const float4* xr = (const float4*)(inputs + ((size_t)n << 10));
    const float4* wr = (const float4*)(kern + ((size_t)tgt << 10));
    float d = 0.f;
#pragma unroll
    for (int it = 0; it < 8; ++it) {
        float4 a = xr[lane + it * 32];
        float4 b = wr[lane + it * 32];
        d += a.x * b.x + a.y * b.y + a.z * b.z + a.w * b.w;
    }
#pragma unroll
    for (int o = 16; o; o >>= 1) d += __shfl_down_sync(0xffffffffu, d, o);
    if (lane == 0) {
        g_true[n] = d + bias[tgt] + neg_log_expected(tgt);
        g_rowsum[n] = 0.f;
    }
}

// ---------------- fused GEMM (bf16 mma.sync) + exp epilogue ----------------
// CTA tile 128x128, 4 warps in 2(M) x 2(N), warp tile 64x64.
// K-chunk 64, 3-stage cp.async pipeline, register fragment double-buffering.
#define SLD 72                         // smem K stride (64 + 8 pad) in bf16
#define A_STG (128 * SLD * 2)          // 18432 B per operand stage
#define NSTG 3
#define OFF_B    (NSTG * A_STG)        // 55296
#define OFF_SROW (2 * NSTG * A_STG)    // 110592
#define SMEM_BYTES (OFF_SROW + 512)
#define NK (PC / 64)                   // 16 K-chunks

__global__ __launch_bounds__(128, 2) void gemm_exp_kernel(
    const int* __restrict__ targets, const int* __restrict__ sampled) {
    extern __shared__ char smem[];
    float* srow = (float*)(smem + OFF_SROW);

    const int tid = threadIdx.x;
    const int lane = tid & 31, warp = tid >> 5;
    const int wm = warp >> 1, wn = warp & 1;       // 2 x 2 warp grid
    const int bm = blockIdx.y * 128, bn = blockIdx.x * 128;

    float acc[4][8][4];
#pragma unroll
    for (int mi = 0; mi < 4; mi++)
#pragma unroll
        for (int ni = 0; ni < 8; ni++)
#pragma unroll
            for (int e = 0; e < 4; e++) acc[mi][ni][e] = 0.f;

    srow[tid] = 0.f;

    uint32_t sbase;
    asm("{ .reg .u64 t; cvta.to.shared.u64 t, %1; cvt.u32.u64 %0, t; }"
        : "=r"(sbase) : "l"(smem));
    const uint32_t sA = sbase;
    const uint32_t sB = sbase + OFF_B;

    // ldmatrix per-lane address components (within tile)
    const int arow  = wm * 64 + (lane & 7) + 8 * ((lane >> 3) & 1);
    const int acoff = (lane >> 4) * 8;
    const int brow  = wn * 64 + (lane & 7) + 8 * (lane >> 4);
    const int bcoff = ((lane >> 3) & 1) * 8;

    // global->shared: 1024 16B chunks per operand per stage, 8 per thread
    const int r0 = tid >> 3, c0 = tid & 7;   // rows r0 + it*16, it=0..7
    const __nv_bfloat16* Ag = g_X + (size_t)(bm + r0) * PC + c0 * 8;
    const __nv_bfloat16* Bg = g_W + (size_t)(bn + r0) * PC + c0 * 8;
    const uint32_t dA = sA + (uint32_t)(r0 * SLD + c0 * 8) * 2;
    const uint32_t dB = sB + (uint32_t)(r0 * SLD + c0 * 8) * 2;

#define LOAD_STAGE(kt_, so_)                                                   \
    do {                                                                       \
        if ((kt_) < NK) {                                                      \
            uint32_t so = (uint32_t)(so_) * A_STG;                             \
            int ko = (kt_) * 64;                                               \
            _Pragma("unroll")                                                  \
            for (int it = 0; it < 8; ++it) {                                   \
                CP_ASYNC16(dA + so + (uint32_t)(it * 16 * SLD * 2),            \
                           Ag + ko + (size_t)it * 16 * PC);                    \
                CP_ASYNC16(dB + so + (uint32_t)(it * 16 * SLD * 2),            \
                           Bg + ko + (size_t)it * 16 * PC);                    \
            }                                                                  \
        }                                                                      \
        asm volatile("cp.async.commit_group;" ::: "memory");                   \
    } while (0)

    uint32_t afr[2][4][4];
    uint32_t bfr[2][8][2];

#define LDFRAG(buf_, ca_, cb_, ks_)                                            \
    do {                                                                       \
        _Pragma("unroll")                                                      \
        for (int mi = 0; mi < 4; mi++)                                         \
            ldm_x4(afr[buf_][mi], (ca_) +                                      \
                (uint32_t)(((arow + mi * 16) * SLD + (ks_) * 16 + acoff) * 2));\
        _Pragma("unroll")                                                      \
        for (int nb = 0; nb < 4; nb++) {                                       \
            uint32_t r[4];                                                     \
            ldm_x4(r, (cb_) +                                                  \
                (uint32_t)(((brow + nb * 16) * SLD + (ks_) * 16 + bcoff) * 2));\
            bfr[buf_][2 * nb][0] = r[0];                                       \
            bfr[buf_][2 * nb][1] = r[1];                                       \
            bfr[buf_][2 * nb + 1][0] = r[2];                                   \
            bfr[buf_][2 * nb + 1][1] = r[3];                                   \
        }                                                                      \
    } while (0)

#define MMA_GROUP(buf_)                                                        \
    do {                                                                       \
        _Pragma("unroll")                                                      \
        for (int mi = 0; mi < 4; mi++)                                         \
            _Pragma("unroll")                                                  \
            for (int ni = 0; ni < 8; ni++)                                     \
                mma_bf16(acc[mi][ni], afr[buf_][mi], bfr[buf_][ni][0],         \
                         bfr[buf_][ni][1]);                                    \
    } while (0)

    // prologue: stages 0,1 in flight; stage 0 ready; preload ks=0 fragments
    LOAD_STAGE(0, 0);
    LOAD_STAGE(1, 1);
    asm volatile("cp.async.wait_group 1;" ::: "memory");
    __syncthreads();

    int s_cur = 0, s_ld = 2;
    uint32_t ca = sA, cb = sB;
    LDFRAG(0, ca, cb, 0);

#pragma unroll 1
    for (int kt = 0; kt < NK; ++kt) {
        // issue loads for stage kt+2 into buffer s_ld (== stage kt-1, fully
        // consumed before the sync at the end of iteration kt-1)
        LOAD_STAGE(kt + 2, s_ld);
        s_ld = (s_ld == 2) ? 0 : s_ld + 1;

#pragma unroll
        for (int ks = 0; ks < 4; ++ks) {
            if (ks < 3) LDFRAG((ks + 1) & 1, ca, cb, ks + 1);
            MMA_GROUP(ks & 1);
        }

        if (kt + 1 < NK) {
            asm volatile("cp.async.wait_group 1;" ::: "memory");
            __syncthreads();
            s_cur = (s_cur == 2) ? 0 : s_cur + 1;
            ca = sA + (uint32_t)s_cur * A_STG;
            cb = sB + (uint32_t)s_cur * A_STG;
            LDFRAG(0, ca, cb, 0);
        }
    }

    // ---- epilogue: corrected logits -> exp -> per-row partial sums ----
    int tg[4][2];
#pragma unroll
    for (int mi = 0; mi < 4; mi++)
#pragma unroll
        for (int h = 0; h < 2; h++)
            tg[mi][h] = targets[bm + wm * 64 + mi * 16 + (lane >> 2) + h * 8];

    float rs[4][2];
#pragma unroll
    for (int mi = 0; mi < 4; mi++) { rs[mi][0] = 0.f; rs[mi][1] = 0.f; }

#pragma unroll
    for (int ni = 0; ni < 8; ni++) {
#pragma unroll
        for (int j = 0; j < 2; j++) {
            int col = bn + wn * 64 + ni * 8 + ((lane & 3) << 1) + j;
            int sid = sampled[col];
            float bc = g_bcorr[col];
#pragma unroll
            for (int mi = 0; mi < 4; mi++) {
#pragma unroll
                for (int h = 0; h < 2; h++) {
                    if (sid != tg[mi][h])
                        rs[mi][h] += __expf(acc[mi][ni][h * 2 + j] + bc);
                }
            }
        }
    }

#pragma unroll
    for (int mi = 0; mi < 4; mi++) {
#pragma unroll
        for (int h = 0; h < 2; h++) {
            float v = rs[mi][h];
            v += __shfl_xor_sync(0xffffffffu, v, 1);
            v += __shfl_xor_sync(0xffffffffu, v, 2);
            if ((lane & 3) == 0)
                atomicAdd(&srow[wm * 64 + mi * 16 + (lane >> 2) + h * 8], v);
        }
    }
    __syncthreads();
    atomicAdd(&g_rowsum[bm + tid], srow[tid]);
}

// ---------------- finalize: per-example loss + mean ----------------
__global__ void finalize_kernel(float* __restrict__ out) {
    __shared__ double sh[32];
    double local = 0.0;
    for (int n = threadIdx.x; n < PN; n += 1024) {
        float t = g_true[n];
        float v = logf(g_rowsum[n] + expf(t)) - t;
        local += (double)v;
    }
#pragma unroll
    for (int o = 16; o; o >>= 1) local += __shfl_down_sync(0xffffffffu, local, o);
    if ((threadIdx.x & 31) == 0) sh[threadIdx.x >> 5] = local;
    __syncthreads();
    if (threadIdx.x < 32) {
        double v = sh[threadIdx.x];
#pragma unroll
        for (int o = 16; o; o >>= 1) v += __shfl_down_sync(0xffffffffu, v, o);
        if (threadIdx.x == 0) out[0] = (float)(v / (double)PN);
    }
}

// ---------------- entry ----------------
extern "C" void kernel_launch(void* const* d_in, const int* in_sizes, int n_in,
                              void* d_out, int out_size) {
    const float* inputs  = (const float*)d_in[0];
    const int*   targets = (const int*)d_in[1];
    const int*   sampled = (const int*)d_in[2];
    const float* kern    = (const float*)d_in[3];
    const float* bias    = (const float*)d_in[4];
    float* out = (float*)d_out;

    static int smem_set = 0;
    if (!smem_set) {
        cudaFuncSetAttribute(gemm_exp_kernel,
                             cudaFuncAttributeMaxDynamicSharedMemorySize, SMEM_BYTES);
        smem_set = 1;
    }

    prep_gather_kernel<<<4096, 256>>>(inputs, sampled, kern);
    prep_bcorr_kernel<<<PS / 256, 256>>>(sampled, bias);
    prep_true_kernel<<<PN / 8, 256>>>(inputs, targets, kern, bias);

    dim3 grid(PS / 128, PN / 128);
    gemm_exp_kernel<<<grid, 128, SMEM_BYTES>>>(targets, sampled);

    finalize_kernel<<<1, 1024>>>(out);
}